// round 1
// baseline (speedup 1.0000x reference)
#include <cuda_runtime.h>

#define NTOK 1024
#define DIM  128
#define BI   8     // i-rows per block
#define BJ   64    // j-chunk

// Scratch for Q, K, V projections (allocation-free rule: __device__ globals)
__device__ float Qg[NTOK * DIM];
__device__ float Kg[NTOK * DIM];
__device__ float Vg[NTOK * DIM];

// ---------------------------------------------------------------------------
// Kernel 1: Q/K/V = x @ W + b   (grid: 32 row-tiles x 3 matrices, 256 thr)
// ---------------------------------------------------------------------------
__global__ __launch_bounds__(256) void qkv_kernel(
    const float* __restrict__ x,
    const float* __restrict__ Wq, const float* __restrict__ bq,
    const float* __restrict__ Wk, const float* __restrict__ bk,
    const float* __restrict__ Wv, const float* __restrict__ bv)
{
    __shared__ float xs[32][DIM];
    const int rt = blockIdx.x;          // 32-row tile
    const int m  = blockIdx.y;          // which matrix
    const float* W  = (m == 0) ? Wq : (m == 1) ? Wk : Wv;
    const float* b  = (m == 0) ? bq : (m == 1) ? bk : bv;
    float* outp     = (m == 0) ? Qg : (m == 1) ? Kg : Vg;

    for (int k = threadIdx.x; k < 32 * DIM; k += 256)
        xs[k >> 7][k & 127] = x[(rt * 32) * DIM + k];
    __syncthreads();

    const int col = threadIdx.x & 127;
    const int rh  = threadIdx.x >> 7;   // 0/1: rows rh*16 .. rh*16+15
    float bias = b[col];
    float acc[16];
#pragma unroll
    for (int r = 0; r < 16; r++) acc[r] = bias;

#pragma unroll 4
    for (int d = 0; d < DIM; d++) {
        float w = W[d * DIM + col];
#pragma unroll
        for (int r = 0; r < 16; r++)
            acc[r] += xs[rh * 16 + r][d] * w;
    }
#pragma unroll
    for (int r = 0; r < 16; r++)
        outp[(rt * 32 + rh * 16 + r) * DIM + col] = acc[r];
}

// ---------------------------------------------------------------------------
// Kernel 2: fused edge-attention.
//   Phase A: e[i][j] = sum_d relu(Q_i[d]+K_j[d]) * W_A[d]
//   softmax rows -> alpha (in smem, in place)
//   Phase B: R_i[d]  = sum_j alpha_ij * relu(Q_i[d]+K_j[d])
//            aV_i[d] = sum_j alpha_ij * V_j[d]
//   Epilogue: out_i = aV_i + R_i @ W_Ev + b_Ev
// ---------------------------------------------------------------------------
__global__ __launch_bounds__(256) void attn_kernel(
    const float* __restrict__ WA,
    const float* __restrict__ WEv,
    const float* __restrict__ bEv,
    float* __restrict__ out)
{
    extern __shared__ float sm[];
    float* es  = sm;                  // BI * NTOK   (logits -> alpha)
    float* Qs  = es + BI * NTOK;      // BI * DIM
    float* WAs = Qs + BI * DIM;       // DIM
    float* KT  = WAs + DIM;           // phase A: DIM x 65 (transposed, padded)
    float* Ks  = KT;                  // phase B: BJ x DIM
    float* Vs  = KT + BJ * DIM;       // phase B: BJ x DIM
    float* Rs  = KT;                  // epilogue: BI x DIM (reuse)

    const int tid = threadIdx.x;
    const int ib0 = blockIdx.x * BI;

    for (int k = tid; k < BI * DIM; k += 256) Qs[k] = Qg[ib0 * DIM + k];
    if (tid < DIM) WAs[tid] = WA[tid];        // W_A is (128,1) contiguous

    // ---------------- Phase A: logits ----------------
    const int jloc = tid & 63;
    const int ig   = tid >> 6;                // 0..3 (constant within warp)
    const float* q0 = Qs + ig * DIM;
    const float* q1 = Qs + (ig + 4) * DIM;

    for (int jc = 0; jc < NTOK; jc += 64) {
        __syncthreads();
        // load K chunk transposed: KT[d][j], pad 65 -> conflict-free
        for (int k = tid; k < 64 * DIM; k += 256) {
            int j = k >> 7, d = k & 127;
            KT[d * 65 + j] = Kg[(jc + j) * DIM + d];
        }
        __syncthreads();
        float e0 = 0.f, e1 = 0.f;
#pragma unroll 8
        for (int d = 0; d < DIM; d++) {
            float kv = KT[d * 65 + jloc];     // lanes: consecutive j -> no conflict
            float wa = WAs[d];                // broadcast
            e0 += fmaxf(q0[d] + kv, 0.f) * wa;   // q broadcast (same i per warp)
            e1 += fmaxf(q1[d] + kv, 0.f) * wa;
        }
        es[ig * NTOK + jc + jloc]       = e0;
        es[(ig + 4) * NTOK + jc + jloc] = e1;
    }
    __syncthreads();

    // ---------------- Softmax: warp w handles row w ----------------
    {
        const int w = tid >> 5, lane = tid & 31;
        float* row = es + w * NTOK;
        float mx = -1e30f;
        for (int j = lane; j < NTOK; j += 32) mx = fmaxf(mx, row[j]);
#pragma unroll
        for (int o = 16; o > 0; o >>= 1) mx = fmaxf(mx, __shfl_xor_sync(0xffffffffu, mx, o));
        float s = 0.f;
        for (int j = lane; j < NTOK; j += 32) {
            float v = __expf(row[j] - mx);
            row[j] = v;
            s += v;
        }
#pragma unroll
        for (int o = 16; o > 0; o >>= 1) s += __shfl_xor_sync(0xffffffffu, s, o);
        float inv = 1.f / s;
        for (int j = lane; j < NTOK; j += 32) row[j] *= inv;
    }
    __syncthreads();

    // ---------------- Phase B: accumulate R and aV ----------------
    // thread: 2 i-rows x 2 adjacent d   (i-reuse halves LDS traffic)
    const int dcol = tid & 63;
    const int rowg = tid >> 6;                // constant within warp
    const int d0 = dcol * 2;
    const int i0 = rowg, i1 = rowg + 4;
    const float q0a = Qs[i0 * DIM + d0], q0b = Qs[i0 * DIM + d0 + 1];
    const float q1a = Qs[i1 * DIM + d0], q1b = Qs[i1 * DIM + d0 + 1];
    float r0a = 0.f, r0b = 0.f, r1a = 0.f, r1b = 0.f;
    float v0a = 0.f, v0b = 0.f, v1a = 0.f, v1b = 0.f;

    for (int jc = 0; jc < NTOK; jc += BJ) {
        __syncthreads();
        for (int k = tid; k < BJ * DIM; k += 256) {
            Ks[k] = Kg[jc * DIM + k];
            Vs[k] = Vg[jc * DIM + k];
        }
        __syncthreads();
#pragma unroll 4
        for (int j = 0; j < BJ; j++) {
            float a0 = es[i0 * NTOK + jc + j];                 // broadcast
            float a1 = es[i1 * NTOK + jc + j];                 // broadcast
            float2 kk = *(const float2*)(Ks + j * DIM + d0);   // LDS.64 conflict-free
            float2 vv = *(const float2*)(Vs + j * DIM + d0);
            r0a += a0 * fmaxf(q0a + kk.x, 0.f);
            r0b += a0 * fmaxf(q0b + kk.y, 0.f);
            r1a += a1 * fmaxf(q1a + kk.x, 0.f);
            r1b += a1 * fmaxf(q1b + kk.y, 0.f);
            v0a += a0 * vv.x;  v0b += a0 * vv.y;
            v1a += a1 * vv.x;  v1b += a1 * vv.y;
        }
    }
    __syncthreads();
    Rs[i0 * DIM + d0] = r0a;  Rs[i0 * DIM + d0 + 1] = r0b;
    Rs[i1 * DIM + d0] = r1a;  Rs[i1 * DIM + d0 + 1] = r1b;
    __syncthreads();

    // ---------------- Epilogue: out = aV + R @ W_Ev + b_Ev ----------------
    float o00 = v0a, o01 = v0b, o10 = v1a, o11 = v1b;
    const float* RsA = Rs + i0 * DIM;
    const float* RsB = Rs + i1 * DIM;
#pragma unroll 4
    for (int dd = 0; dd < DIM; dd++) {
        float2 w = *(const float2*)(WEv + dd * DIM + d0);   // coalesced, L1-resident
        float ra = RsA[dd];                                 // broadcast
        float rb = RsB[dd];
        o00 += ra * w.x;  o01 += ra * w.y;
        o10 += rb * w.x;  o11 += rb * w.y;
    }
    float ba = bEv[d0], bb = bEv[d0 + 1];
    out[(ib0 + i0) * DIM + d0]     = o00 + ba;
    out[(ib0 + i0) * DIM + d0 + 1] = o01 + bb;
    out[(ib0 + i1) * DIM + d0]     = o10 + ba;
    out[(ib0 + i1) * DIM + d0 + 1] = o11 + bb;
}

// ---------------------------------------------------------------------------
static const int ATTN_SMEM_BYTES = (BI * NTOK + BI * DIM + DIM + 2 * BJ * DIM) * (int)sizeof(float);

extern "C" void kernel_launch(void* const* d_in, const int* in_sizes, int n_in,
                              void* d_out, int out_size)
{
    const float* x   = (const float*)d_in[0];
    const float* WQ  = (const float*)d_in[1];
    const float* bQ  = (const float*)d_in[2];
    const float* WK  = (const float*)d_in[3];
    const float* bK  = (const float*)d_in[4];
    const float* WV  = (const float*)d_in[5];
    const float* bV  = (const float*)d_in[6];
    const float* WEv = (const float*)d_in[7];
    const float* bEv = (const float*)d_in[8];
    const float* WA  = (const float*)d_in[9];
    // d_in[10] = b_A: cancels exactly in softmax; unused.
    float* out = (float*)d_out;

    cudaFuncSetAttribute(attn_kernel, cudaFuncAttributeMaxDynamicSharedMemorySize,
                         ATTN_SMEM_BYTES);

    qkv_kernel<<<dim3(32, 3), 256>>>(x, WQ, bQ, WK, bK, WV, bV);
    attn_kernel<<<NTOK / BI, 256, ATTN_SMEM_BYTES>>>(WA, WEv, bEv, out);
}

// round 2
// speedup vs baseline: 1.3912x; 1.3912x over previous
#include <cuda_runtime.h>

#define NTOK   1024
#define DIM    128
#define BI     8      // i-rows per block
#define BJ     32     // j-chunk per smem tile
#define NSPLIT 4      // j-splits
#define JSPAN  (NTOK / NSPLIT)   // 256 j per split

// Scratch (__device__ globals: allocation-free rule)
__device__ float Qg[NTOK * DIM];
__device__ float Kg[NTOK * DIM];
__device__ float Vg[NTOK * DIM];
__device__ float Rpart[NSPLIT][NTOK][DIM];   // sum_j p_ij * relu(Q_i+K_j)
__device__ float Vpart[NSPLIT][NTOK][DIM];   // sum_j p_ij * V_j
__device__ float Mpart[NSPLIT][NTOK];        // split-local max
__device__ float Spart[NSPLIT][NTOK];        // split-local sum of p

// ---------------------------------------------------------------------------
// Kernel 1: Q/K/V = x @ W + b.  grid (64 row-tiles, 3 matrices), 256 thr.
// Each block: 16 rows. thread: 2 cols x 4 rows.
// ---------------------------------------------------------------------------
__global__ __launch_bounds__(256) void qkv_kernel(
    const float* __restrict__ x,
    const float* __restrict__ Wq, const float* __restrict__ bq,
    const float* __restrict__ Wk, const float* __restrict__ bk,
    const float* __restrict__ Wv, const float* __restrict__ bv)
{
    __shared__ float xs[16][DIM];
    const int rt = blockIdx.x;           // 16-row tile
    const int m  = blockIdx.y;
    const float* W = (m == 0) ? Wq : (m == 1) ? Wk : Wv;
    const float* b = (m == 0) ? bq : (m == 1) ? bk : bv;
    float* outp    = (m == 0) ? Qg : (m == 1) ? Kg : Vg;

    for (int k = threadIdx.x; k < 16 * DIM; k += 256)
        xs[k >> 7][k & 127] = x[(rt * 16) * DIM + k];
    __syncthreads();

    const int c0 = (threadIdx.x & 63) * 2;
    const int rg = threadIdx.x >> 6;          // 0..3 -> rows rg*4..rg*4+3
    float2 bias = *(const float2*)(b + c0);
    float accx[4], accy[4];
#pragma unroll
    for (int r = 0; r < 4; r++) { accx[r] = bias.x; accy[r] = bias.y; }

#pragma unroll 4
    for (int d = 0; d < DIM; d++) {
        float2 w = *(const float2*)(W + d * DIM + c0);
#pragma unroll
        for (int r = 0; r < 4; r++) {
            float xv = xs[rg * 4 + r][d];
            accx[r] += xv * w.x;
            accy[r] += xv * w.y;
        }
    }
#pragma unroll
    for (int r = 0; r < 4; r++) {
        float2 o = make_float2(accx[r], accy[r]);
        *(float2*)(outp + (rt * 16 + rg * 4 + r) * DIM + c0) = o;
    }
}

// ---------------------------------------------------------------------------
// Kernel 2: per-(i-tile, j-split) partial attention.
//   Phase A: e[i][j] = sum_d relu(Q_i+K_j)*W_A  for the split's 256 j
//   split-local softmax: p = exp(e - m_split), record m_split, s_split
//   Phase B: Rpart = sum_j p * relu(Q_i+K_j),  Vpart = sum_j p * V_j
// ---------------------------------------------------------------------------
__global__ __launch_bounds__(256) void attn_partial(const float* __restrict__ WA)
{
    extern __shared__ float sm[];
    float* es  = sm;                       // BI * JSPAN = 2048
    float* Qs  = es + BI * JSPAN;          // BI * DIM   = 1024
    float* WAs = Qs + BI * DIM;            // DIM
    float* buf = WAs + DIM;                // max(128*33, 2*BJ*DIM) = 8192
    float* KT  = buf;                      // phase A: [DIM][33] transposed
    float* Ks  = buf;                      // phase B: [BJ][DIM]
    float* Vs  = buf + BJ * DIM;           // phase B: [BJ][DIM]

    const int tid = threadIdx.x;
    const int ib0 = blockIdx.x * BI;
    const int sp  = blockIdx.y;
    const int js0 = sp * JSPAN;

    for (int k = tid; k < BI * DIM; k += 256) Qs[k] = Qg[ib0 * DIM + k];
    if (tid < DIM) WAs[tid] = WA[tid];

    // ---------------- Phase A: logits for this split ----------------
    const int jA = tid & 31;
    const int iA = tid >> 5;               // warp-uniform
    const float* qrow = Qs + iA * DIM;

    for (int jc = 0; jc < JSPAN; jc += BJ) {
        __syncthreads();
        for (int k = tid; k < BJ * DIM; k += 256) {
            int j = k >> 7, d = k & 127;   // d fast: coalesced LDG, conflict-free STS
            KT[d * 33 + j] = Kg[(js0 + jc + j) * DIM + d];
        }
        __syncthreads();
        float e = 0.f;
#pragma unroll 8
        for (int d = 0; d < DIM; d++)
            e += fmaxf(qrow[d] + KT[d * 33 + jA], 0.f) * WAs[d];
        es[iA * JSPAN + jc + jA] = e;
    }
    __syncthreads();

    // ---------------- split-local softmax: warp w -> row w ----------------
    {
        const int w = tid >> 5, lane = tid & 31;
        float* row = es + w * JSPAN;
        float mx = -1e30f;
#pragma unroll
        for (int j = lane; j < JSPAN; j += 32) mx = fmaxf(mx, row[j]);
#pragma unroll
        for (int o = 16; o > 0; o >>= 1) mx = fmaxf(mx, __shfl_xor_sync(0xffffffffu, mx, o));
        float s = 0.f;
#pragma unroll
        for (int j = lane; j < JSPAN; j += 32) {
            float v = __expf(row[j] - mx);
            row[j] = v;                    // keep UNNORMALIZED p
            s += v;
        }
#pragma unroll
        for (int o = 16; o > 0; o >>= 1) s += __shfl_xor_sync(0xffffffffu, s, o);
        if (lane == 0) {
            Mpart[sp][ib0 + w] = mx;
            Spart[sp][ib0 + w] = s;
        }
    }

    // ---------------- Phase B: partial R and aV ----------------
    const int d0 = (tid & 63) * 2;
    const int ig = tid >> 6;               // warp-uniform
    const int i0 = ig, i1 = ig + 4;
    const float q0a = Qs[i0 * DIM + d0], q0b = Qs[i0 * DIM + d0 + 1];
    const float q1a = Qs[i1 * DIM + d0], q1b = Qs[i1 * DIM + d0 + 1];
    float r0a = 0.f, r0b = 0.f, r1a = 0.f, r1b = 0.f;
    float v0a = 0.f, v0b = 0.f, v1a = 0.f, v1b = 0.f;

    for (int jc = 0; jc < JSPAN; jc += BJ) {
        __syncthreads();
        for (int k = tid; k < BJ * DIM; k += 256) {
            Ks[k] = Kg[(js0 + jc) * DIM + k];   // layout matches: direct copy
            Vs[k] = Vg[(js0 + jc) * DIM + k];
        }
        __syncthreads();
#pragma unroll 4
        for (int j = 0; j < BJ; j++) {
            float a0 = es[i0 * JSPAN + jc + j];                // broadcast
            float a1 = es[i1 * JSPAN + jc + j];
            float2 kk = *(const float2*)(Ks + j * DIM + d0);   // conflict-free
            float2 vv = *(const float2*)(Vs + j * DIM + d0);
            r0a += a0 * fmaxf(q0a + kk.x, 0.f);
            r0b += a0 * fmaxf(q0b + kk.y, 0.f);
            r1a += a1 * fmaxf(q1a + kk.x, 0.f);
            r1b += a1 * fmaxf(q1b + kk.y, 0.f);
            v0a += a0 * vv.x;  v0b += a0 * vv.y;
            v1a += a1 * vv.x;  v1b += a1 * vv.y;
        }
    }

    *(float2*)&Rpart[sp][ib0 + i0][d0] = make_float2(r0a, r0b);
    *(float2*)&Rpart[sp][ib0 + i1][d0] = make_float2(r1a, r1b);
    *(float2*)&Vpart[sp][ib0 + i0][d0] = make_float2(v0a, v0b);
    *(float2*)&Vpart[sp][ib0 + i1][d0] = make_float2(v1a, v1b);
}

// ---------------------------------------------------------------------------
// Kernel 3: combine splits + epilogue out = aV + R @ W_Ev + b_Ev
// ---------------------------------------------------------------------------
__global__ __launch_bounds__(256) void combine_kernel(
    const float* __restrict__ WEv,
    const float* __restrict__ bEv,
    float* __restrict__ out)
{
    __shared__ float Rs[BI * DIM];
    const int tid = threadIdx.x;
    const int ib0 = blockIdx.x * BI;
    const int d0 = (tid & 63) * 2;
    const int ig = tid >> 6;
    const int i0 = ig, i1 = ig + 4;
    const int gi0 = ib0 + i0, gi1 = ib0 + i1;

    float m0 = -1e30f, m1 = -1e30f;
#pragma unroll
    for (int p = 0; p < NSPLIT; p++) {
        m0 = fmaxf(m0, Mpart[p][gi0]);
        m1 = fmaxf(m1, Mpart[p][gi1]);
    }
    float s0 = 0.f, s1 = 0.f;
    float r0a = 0.f, r0b = 0.f, r1a = 0.f, r1b = 0.f;
    float v0a = 0.f, v0b = 0.f, v1a = 0.f, v1b = 0.f;
#pragma unroll
    for (int p = 0; p < NSPLIT; p++) {
        float c0 = __expf(Mpart[p][gi0] - m0);
        float c1 = __expf(Mpart[p][gi1] - m1);
        s0 += Spart[p][gi0] * c0;
        s1 += Spart[p][gi1] * c1;
        float2 rp0 = *(const float2*)&Rpart[p][gi0][d0];
        float2 rp1 = *(const float2*)&Rpart[p][gi1][d0];
        float2 vp0 = *(const float2*)&Vpart[p][gi0][d0];
        float2 vp1 = *(const float2*)&Vpart[p][gi1][d0];
        r0a += c0 * rp0.x;  r0b += c0 * rp0.y;
        r1a += c1 * rp1.x;  r1b += c1 * rp1.y;
        v0a += c0 * vp0.x;  v0b += c0 * vp0.y;
        v1a += c1 * vp1.x;  v1b += c1 * vp1.y;
    }
    float inv0 = 1.f / s0, inv1 = 1.f / s1;
    r0a *= inv0;  r0b *= inv0;  r1a *= inv1;  r1b *= inv1;
    v0a *= inv0;  v0b *= inv0;  v1a *= inv1;  v1b *= inv1;

    Rs[i0 * DIM + d0] = r0a;  Rs[i0 * DIM + d0 + 1] = r0b;
    Rs[i1 * DIM + d0] = r1a;  Rs[i1 * DIM + d0 + 1] = r1b;
    __syncthreads();

    float o00 = v0a, o01 = v0b, o10 = v1a, o11 = v1b;
    const float* RsA = Rs + i0 * DIM;
    const float* RsB = Rs + i1 * DIM;
#pragma unroll 4
    for (int dd = 0; dd < DIM; dd++) {
        float2 w = *(const float2*)(WEv + dd * DIM + d0);
        float ra = RsA[dd];
        float rb = RsB[dd];
        o00 += ra * w.x;  o01 += ra * w.y;
        o10 += rb * w.x;  o11 += rb * w.y;
    }
    float ba = bEv[d0], bb = bEv[d0 + 1];
    *(float2*)(out + gi0 * DIM + d0) = make_float2(o00 + ba, o01 + bb);
    *(float2*)(out + gi1 * DIM + d0) = make_float2(o10 + ba, o11 + bb);
}

// ---------------------------------------------------------------------------
static const int ATTN_SMEM_BYTES =
    (BI * JSPAN + BI * DIM + DIM + 2 * BJ * DIM) * (int)sizeof(float);

extern "C" void kernel_launch(void* const* d_in, const int* in_sizes, int n_in,
                              void* d_out, int out_size)
{
    const float* x   = (const float*)d_in[0];
    const float* WQ  = (const float*)d_in[1];
    const float* bQ  = (const float*)d_in[2];
    const float* WK  = (const float*)d_in[3];
    const float* bK  = (const float*)d_in[4];
    const float* WV  = (const float*)d_in[5];
    const float* bV  = (const float*)d_in[6];
    const float* WEv = (const float*)d_in[7];
    const float* bEv = (const float*)d_in[8];
    const float* WA  = (const float*)d_in[9];
    // d_in[10] = b_A: cancels exactly in softmax; unused.
    float* out = (float*)d_out;

    cudaFuncSetAttribute(attn_partial, cudaFuncAttributeMaxDynamicSharedMemorySize,
                         ATTN_SMEM_BYTES);

    qkv_kernel<<<dim3(64, 3), 256>>>(x, WQ, bQ, WK, bK, WV, bV);
    attn_partial<<<dim3(NTOK / BI, NSPLIT), 256, ATTN_SMEM_BYTES>>>(WA);
    combine_kernel<<<NTOK / BI, 256>>>(WEv, bEv, out);
}

// round 3
// speedup vs baseline: 1.6127x; 1.1592x over previous
#include <cuda_runtime.h>

#define NTOK   1024
#define DIM    128
#define BI     8      // i-rows per block
#define BJ     32     // j-chunk, phase B
#define BJA    64     // j-chunk, phase A
#define NSPLIT 4
#define JSPAN  (NTOK / NSPLIT)   // 256

// Scratch (__device__ globals: allocation-free rule)
__device__ float Qg[NTOK * DIM];
__device__ float Kg[NTOK * DIM];
__device__ float Vg[NTOK * DIM];
__device__ float Rpart[NSPLIT][NTOK][DIM];
__device__ float Vpart[NSPLIT][NTOK][DIM];
__device__ float Mpart[NSPLIT][NTOK];
__device__ float Spart[NSPLIT][NTOK];

// ---------------------------------------------------------------------------
// Kernel 1: Q/K/V = x @ W + b.  grid (128 row-tiles, 3), 256 thr.
// 8 rows/block; thread: 2 rows x 2 cols. unroll 16 -> high LDG MLP.
// ---------------------------------------------------------------------------
__global__ __launch_bounds__(256) void qkv_kernel(
    const float* __restrict__ x,
    const float* __restrict__ Wq, const float* __restrict__ bq,
    const float* __restrict__ Wk, const float* __restrict__ bk,
    const float* __restrict__ Wv, const float* __restrict__ bv)
{
    __shared__ float xs[8][DIM];
    const int rt = blockIdx.x;           // 8-row tile
    const int m  = blockIdx.y;
    const float* W = (m == 0) ? Wq : (m == 1) ? Wk : Wv;
    const float* b = (m == 0) ? bq : (m == 1) ? bk : bv;
    float* outp    = (m == 0) ? Qg : (m == 1) ? Kg : Vg;

    for (int k = threadIdx.x; k < 8 * DIM; k += 256)
        xs[k >> 7][k & 127] = x[(rt * 8) * DIM + k];
    __syncthreads();

    const int c0 = (threadIdx.x & 63) * 2;
    const int r0 = (threadIdx.x >> 6) * 2;    // warp-uniform row pair
    float2 bias = *(const float2*)(b + c0);
    float a0x = bias.x, a0y = bias.y, a1x = bias.x, a1y = bias.y;

#pragma unroll 16
    for (int d = 0; d < DIM; d++) {
        float2 w = *(const float2*)(W + d * DIM + c0);
        float x0 = xs[r0][d];
        float x1 = xs[r0 + 1][d];
        a0x += x0 * w.x;  a0y += x0 * w.y;
        a1x += x1 * w.x;  a1y += x1 * w.y;
    }
    *(float2*)(outp + (rt * 8 + r0) * DIM + c0)     = make_float2(a0x, a0y);
    *(float2*)(outp + (rt * 8 + r0 + 1) * DIM + c0) = make_float2(a1x, a1y);
}

// ---------------------------------------------------------------------------
// Kernel 2: per-(i-tile, j-split) partial attention.
// ---------------------------------------------------------------------------
__global__ __launch_bounds__(256) void attn_partial(const float* __restrict__ WA)
{
    extern __shared__ float sm[];
    float* es  = sm;                       // BI * JSPAN = 2048
    float* Qs  = es + BI * JSPAN;          // BI * DIM = 1024
    float* WAs = Qs + BI * DIM;            // DIM
    float* buf = WAs + DIM;                // max(128*65, 2*BJ*DIM) = 8320
    float* KT  = buf;                      // phase A: [DIM][65]
    float* Ks  = buf;                      // phase B: [BJ][DIM]
    float* Vs  = buf + BJ * DIM;

    const int tid = threadIdx.x;
    const int ib0 = blockIdx.x * BI;
    const int sp  = blockIdx.y;
    const int js0 = sp * JSPAN;

    for (int k = tid; k < BI * DIM; k += 256) Qs[k] = Qg[ib0 * DIM + k];
    if (tid < DIM) WAs[tid] = WA[tid];

    // ---------------- Phase A: logits (2 j's per thread per chunk) --------
    const int jA = tid & 31;
    const int iA = tid >> 5;               // warp-uniform i row
    const float* qrow = Qs + iA * DIM;

    for (int jc = 0; jc < JSPAN; jc += BJA) {
        __syncthreads();
        for (int k = tid; k < BJA * DIM; k += 256) {
            int j = k >> 7, d = k & 127;   // coalesced LDG, conflict-free STS
            KT[d * 65 + j] = Kg[(js0 + jc + j) * DIM + d];
        }
        __syncthreads();
        float e0 = 0.f, e1 = 0.f;
#pragma unroll 8
        for (int d = 0; d < DIM; d++) {
            float q  = qrow[d];            // broadcast
            float wa = WAs[d];             // broadcast
            float k0 = KT[d * 65 + jA];
            float k1 = KT[d * 65 + jA + 32];
            e0 += fmaxf(q + k0, 0.f) * wa;
            e1 += fmaxf(q + k1, 0.f) * wa;
        }
        es[iA * JSPAN + jc + jA]      = e0;
        es[iA * JSPAN + jc + jA + 32] = e1;
    }
    __syncthreads();

    // ---------------- split-local softmax: warp w -> row w ----------------
    {
        const int w = tid >> 5, lane = tid & 31;
        float* row = es + w * JSPAN;
        float mx = -1e30f;
#pragma unroll
        for (int j = lane; j < JSPAN; j += 32) mx = fmaxf(mx, row[j]);
#pragma unroll
        for (int o = 16; o > 0; o >>= 1) mx = fmaxf(mx, __shfl_xor_sync(0xffffffffu, mx, o));
        float s = 0.f;
#pragma unroll
        for (int j = lane; j < JSPAN; j += 32) {
            float v = __expf(row[j] - mx);
            row[j] = v;                    // unnormalized p
            s += v;
        }
#pragma unroll
        for (int o = 16; o > 0; o >>= 1) s += __shfl_xor_sync(0xffffffffu, s, o);
        if (lane == 0) {
            Mpart[sp][ib0 + w] = mx;
            Spart[sp][ib0 + w] = s;
        }
    }

    // ---------------- Phase B: partial R and aV ----------------
    const int d0 = (tid & 63) * 2;
    const int ig = tid >> 6;               // warp-uniform
    const int i0 = ig, i1 = ig + 4;
    const float q0a = Qs[i0 * DIM + d0], q0b = Qs[i0 * DIM + d0 + 1];
    const float q1a = Qs[i1 * DIM + d0], q1b = Qs[i1 * DIM + d0 + 1];
    float r0a = 0.f, r0b = 0.f, r1a = 0.f, r1b = 0.f;
    float v0a = 0.f, v0b = 0.f, v1a = 0.f, v1b = 0.f;

    for (int jc = 0; jc < JSPAN; jc += BJ) {
        __syncthreads();
        for (int k = tid; k < BJ * DIM; k += 256) {
            Ks[k] = Kg[(js0 + jc) * DIM + k];
            Vs[k] = Vg[(js0 + jc) * DIM + k];
        }
        __syncthreads();
#pragma unroll 4
        for (int j = 0; j < BJ; j++) {
            float a0 = es[i0 * JSPAN + jc + j];                // broadcast
            float a1 = es[i1 * JSPAN + jc + j];
            float2 kk = *(const float2*)(Ks + j * DIM + d0);   // conflict-free
            float2 vv = *(const float2*)(Vs + j * DIM + d0);
            r0a += a0 * fmaxf(q0a + kk.x, 0.f);
            r0b += a0 * fmaxf(q0b + kk.y, 0.f);
            r1a += a1 * fmaxf(q1a + kk.x, 0.f);
            r1b += a1 * fmaxf(q1b + kk.y, 0.f);
            v0a += a0 * vv.x;  v0b += a0 * vv.y;
            v1a += a1 * vv.x;  v1b += a1 * vv.y;
        }
    }

    *(float2*)&Rpart[sp][ib0 + i0][d0] = make_float2(r0a, r0b);
    *(float2*)&Rpart[sp][ib0 + i1][d0] = make_float2(r1a, r1b);
    *(float2*)&Vpart[sp][ib0 + i0][d0] = make_float2(v0a, v0b);
    *(float2*)&Vpart[sp][ib0 + i1][d0] = make_float2(v1a, v1b);
}

// ---------------------------------------------------------------------------
// Kernel 3: combine splits + epilogue out = aV + R @ W_Ev + b_Ev
// ---------------------------------------------------------------------------
__global__ __launch_bounds__(256) void combine_kernel(
    const float* __restrict__ WEv,
    const float* __restrict__ bEv,
    float* __restrict__ out)
{
    __shared__ float Rs[BI * DIM];
    const int tid = threadIdx.x;
    const int ib0 = blockIdx.x * BI;
    const int d0 = (tid & 63) * 2;
    const int ig = tid >> 6;
    const int i0 = ig, i1 = ig + 4;
    const int gi0 = ib0 + i0, gi1 = ib0 + i1;

    float m0 = -1e30f, m1 = -1e30f;
#pragma unroll
    for (int p = 0; p < NSPLIT; p++) {
        m0 = fmaxf(m0, Mpart[p][gi0]);
        m1 = fmaxf(m1, Mpart[p][gi1]);
    }
    float s0 = 0.f, s1 = 0.f;
    float r0a = 0.f, r0b = 0.f, r1a = 0.f, r1b = 0.f;
    float v0a = 0.f, v0b = 0.f, v1a = 0.f, v1b = 0.f;
#pragma unroll
    for (int p = 0; p < NSPLIT; p++) {
        float c0 = __expf(Mpart[p][gi0] - m0);
        float c1 = __expf(Mpart[p][gi1] - m1);
        s0 += Spart[p][gi0] * c0;
        s1 += Spart[p][gi1] * c1;
        float2 rp0 = *(const float2*)&Rpart[p][gi0][d0];
        float2 rp1 = *(const float2*)&Rpart[p][gi1][d0];
        float2 vp0 = *(const float2*)&Vpart[p][gi0][d0];
        float2 vp1 = *(const float2*)&Vpart[p][gi1][d0];
        r0a += c0 * rp0.x;  r0b += c0 * rp0.y;
        r1a += c1 * rp1.x;  r1b += c1 * rp1.y;
        v0a += c0 * vp0.x;  v0b += c0 * vp0.y;
        v1a += c1 * vp1.x;  v1b += c1 * vp1.y;
    }
    float inv0 = 1.f / s0, inv1 = 1.f / s1;
    r0a *= inv0;  r0b *= inv0;  r1a *= inv1;  r1b *= inv1;
    v0a *= inv0;  v0b *= inv0;  v1a *= inv1;  v1b *= inv1;

    Rs[i0 * DIM + d0] = r0a;  Rs[i0 * DIM + d0 + 1] = r0b;
    Rs[i1 * DIM + d0] = r1a;  Rs[i1 * DIM + d0 + 1] = r1b;
    __syncthreads();

    float o00 = v0a, o01 = v0b, o10 = v1a, o11 = v1b;
    const float* RsA = Rs + i0 * DIM;
    const float* RsB = Rs + i1 * DIM;
#pragma unroll 8
    for (int dd = 0; dd < DIM; dd++) {
        float2 w = *(const float2*)(WEv + dd * DIM + d0);
        float ra = RsA[dd];
        float rb = RsB[dd];
        o00 += ra * w.x;  o01 += ra * w.y;
        o10 += rb * w.x;  o11 += rb * w.y;
    }
    float ba = bEv[d0], bb = bEv[d0 + 1];
    *(float2*)(out + gi0 * DIM + d0) = make_float2(o00 + ba, o01 + bb);
    *(float2*)(out + gi1 * DIM + d0) = make_float2(o10 + ba, o11 + bb);
}

// ---------------------------------------------------------------------------
static const int ATTN_SMEM_BYTES =
    (BI * JSPAN + BI * DIM + DIM + BJA * 65 + (BJA & 1)) * (int)sizeof(float)
    > (BI * JSPAN + BI * DIM + DIM + 2 * BJ * DIM) * (int)sizeof(float)
    ? (BI * JSPAN + BI * DIM + DIM + DIM * 65) * (int)sizeof(float)
    : (BI * JSPAN + BI * DIM + DIM + 2 * BJ * DIM) * (int)sizeof(float);

extern "C" void kernel_launch(void* const* d_in, const int* in_sizes, int n_in,
                              void* d_out, int out_size)
{
    const float* x   = (const float*)d_in[0];
    const float* WQ  = (const float*)d_in[1];
    const float* bQ  = (const float*)d_in[2];
    const float* WK  = (const float*)d_in[3];
    const float* bK  = (const float*)d_in[4];
    const float* WV  = (const float*)d_in[5];
    const float* bV  = (const float*)d_in[6];
    const float* WEv = (const float*)d_in[7];
    const float* bEv = (const float*)d_in[8];
    const float* WA  = (const float*)d_in[9];
    // d_in[10] = b_A: cancels in softmax; unused.
    float* out = (float*)d_out;

    // smem: es + Qs + WAs + max(KT[128][65], Ks+Vs)
    const int smem_bytes =
        (BI * JSPAN + BI * DIM + DIM + DIM * 65) * (int)sizeof(float);

    cudaFuncSetAttribute(attn_partial, cudaFuncAttributeMaxDynamicSharedMemorySize,
                         smem_bytes);

    qkv_kernel<<<dim3(128, 3), 256>>>(x, WQ, bQ, WK, bK, WV, bV);
    attn_partial<<<dim3(NTOK / BI, NSPLIT), 256, smem_bytes>>>(WA);
    combine_kernel<<<NTOK / BI, 256>>>(WEv, bEv, out);
}

// round 4
// speedup vs baseline: 1.7121x; 1.0616x over previous
#include <cuda_runtime.h>

#define NTOK   1024
#define DIM    128
#define BI     8
#define NSPLIT 4
#define JSPAN  (NTOK / NSPLIT)   // 256

// Scratch (__device__ globals: allocation-free rule)
__device__ float Qg[NTOK * DIM];
__device__ float Kg[NTOK * DIM];
__device__ float Vg[NTOK * DIM];
__device__ float Rpart[NSPLIT][NTOK][DIM];
__device__ float Vpart[NSPLIT][NTOK][DIM];
__device__ float Mpart[NSPLIT][NTOK];
__device__ float Spart[NSPLIT][NTOK];

// ---------------------------------------------------------------------------
// Kernel 1: Q/K/V = x @ W + b.  grid (128, 3), 256 thr.
// 8 rows/block. thread = 1 row x 4 cols, LDG.128 W stream.
// ---------------------------------------------------------------------------
__global__ __launch_bounds__(256) void qkv_kernel(
    const float* __restrict__ x,
    const float* __restrict__ Wq, const float* __restrict__ bq,
    const float* __restrict__ Wk, const float* __restrict__ bk,
    const float* __restrict__ Wv, const float* __restrict__ bv)
{
    __shared__ float xs[8 * DIM];
    const int tid = threadIdx.x;
    const int rt = blockIdx.x;
    const int m  = blockIdx.y;
    const float* W = (m == 0) ? Wq : (m == 1) ? Wk : Wv;
    const float* b = (m == 0) ? bq : (m == 1) ? bk : bv;
    float* outp    = (m == 0) ? Qg : (m == 1) ? Kg : Vg;

    ((float4*)xs)[tid] = ((const float4*)(x + rt * 8 * DIM))[tid];  // 1024 floats
    __syncthreads();

    const int row = tid >> 5;
    const int c0  = (tid & 31) * 4;
    float4 acc = *(const float4*)(b + c0);
    const float* xr = xs + row * DIM;

#pragma unroll 8
    for (int d = 0; d < DIM; d++) {
        float4 w = *(const float4*)(W + d * DIM + c0);
        float xv = xr[d];
        acc.x += xv * w.x;  acc.y += xv * w.y;
        acc.z += xv * w.z;  acc.w += xv * w.w;
    }
    *(float4*)(outp + (rt * 8 + row) * DIM + c0) = acc;
}

// ---------------------------------------------------------------------------
// Kernel 2: per-(i-tile, j-split) partial attention. 3 barriers total.
// ---------------------------------------------------------------------------
__global__ __launch_bounds__(256) void attn_partial(const float* __restrict__ WA)
{
    __shared__ float es[BI * JSPAN];   // 8 KB
    __shared__ float Qs[BI * DIM];     // 4 KB
    __shared__ float WAs[DIM];

    const int tid = threadIdx.x;
    const int ib0 = blockIdx.x * BI;
    const int sp  = blockIdx.y;
    const int js0 = sp * JSPAN;

    ((float4*)Qs)[tid] = ((const float4*)(Qg + ib0 * DIM))[tid];   // 1024 floats
    if (tid < DIM) WAs[tid] = WA[tid];
    __syncthreads();

    // ---------------- Phase A: thread owns one j; K row streamed via LDG ----
    {
        float e[BI];
#pragma unroll
        for (int i = 0; i < BI; i++) e[i] = 0.f;
        const float* krow = Kg + (js0 + tid) * DIM;

        for (int db = 0; db < DIM; db += 16) {
            float4 k0 = *(const float4*)(krow + db);
            float4 k1 = *(const float4*)(krow + db + 4);
            float4 k2 = *(const float4*)(krow + db + 8);
            float4 k3 = *(const float4*)(krow + db + 12);
            float kv[16];
            kv[0]=k0.x; kv[1]=k0.y; kv[2]=k0.z; kv[3]=k0.w;
            kv[4]=k1.x; kv[5]=k1.y; kv[6]=k1.z; kv[7]=k1.w;
            kv[8]=k2.x; kv[9]=k2.y; kv[10]=k2.z; kv[11]=k2.w;
            kv[12]=k3.x; kv[13]=k3.y; kv[14]=k3.z; kv[15]=k3.w;
#pragma unroll
            for (int t = 0; t < 16; t++) {
                float wa = WAs[db + t];                    // broadcast
                float kk = kv[t];
#pragma unroll
                for (int i = 0; i < BI; i++)               // Qs broadcast
                    e[i] += fmaxf(Qs[i * DIM + db + t] + kk, 0.f) * wa;
            }
        }
#pragma unroll
        for (int i = 0; i < BI; i++) es[i * JSPAN + tid] = e[i];
    }
    __syncthreads();

    // ---------------- split-local softmax: warp w -> row w ----------------
    {
        const int w = tid >> 5, lane = tid & 31;
        float* row = es + w * JSPAN;
        float mx = -1e30f;
#pragma unroll
        for (int j = lane; j < JSPAN; j += 32) mx = fmaxf(mx, row[j]);
#pragma unroll
        for (int o = 16; o > 0; o >>= 1) mx = fmaxf(mx, __shfl_xor_sync(0xffffffffu, mx, o));
        float s = 0.f;
#pragma unroll
        for (int j = lane; j < JSPAN; j += 32) {
            float v = __expf(row[j] - mx);
            row[j] = v;                                    // unnormalized p
            s += v;
        }
#pragma unroll
        for (int o = 16; o > 0; o >>= 1) s += __shfl_xor_sync(0xffffffffu, s, o);
        if (lane == 0) {
            Mpart[sp][ib0 + w] = mx;
            Spart[sp][ib0 + w] = s;
        }
    }
    __syncthreads();

    // ---------------- Phase B: direct-LDG K/V rows, lanes over d ----------
    const int d0 = (tid & 63) * 2;
    const int ig = tid >> 6;               // warp-uniform
    const int i0 = ig, i1 = ig + 4;
    const float q0a = Qs[i0 * DIM + d0], q0b = Qs[i0 * DIM + d0 + 1];
    const float q1a = Qs[i1 * DIM + d0], q1b = Qs[i1 * DIM + d0 + 1];
    float r0a = 0.f, r0b = 0.f, r1a = 0.f, r1b = 0.f;
    float v0a = 0.f, v0b = 0.f, v1a = 0.f, v1b = 0.f;

    const float* kr  = Kg + js0 * DIM + d0;
    const float* vr  = Vg + js0 * DIM + d0;
    const float* ea0 = es + i0 * JSPAN;
    const float* ea1 = es + i1 * JSPAN;

#pragma unroll 4
    for (int j = 0; j < JSPAN; j += 2) {
        float2 a0 = *(const float2*)(ea0 + j);             // smem broadcast
        float2 a1 = *(const float2*)(ea1 + j);
        float2 kA = *(const float2*)(kr + j * DIM);        // L1-resident
        float2 kB = *(const float2*)(kr + j * DIM + DIM);
        float2 vA = *(const float2*)(vr + j * DIM);
        float2 vB = *(const float2*)(vr + j * DIM + DIM);

        r0a += a0.x * fmaxf(q0a + kA.x, 0.f);
        r0b += a0.x * fmaxf(q0b + kA.y, 0.f);
        r1a += a1.x * fmaxf(q1a + kA.x, 0.f);
        r1b += a1.x * fmaxf(q1b + kA.y, 0.f);
        v0a += a0.x * vA.x;  v0b += a0.x * vA.y;
        v1a += a1.x * vA.x;  v1b += a1.x * vA.y;

        r0a += a0.y * fmaxf(q0a + kB.x, 0.f);
        r0b += a0.y * fmaxf(q0b + kB.y, 0.f);
        r1a += a1.y * fmaxf(q1a + kB.x, 0.f);
        r1b += a1.y * fmaxf(q1b + kB.y, 0.f);
        v0a += a0.y * vB.x;  v0b += a0.y * vB.y;
        v1a += a1.y * vB.x;  v1b += a1.y * vB.y;
    }

    *(float2*)&Rpart[sp][ib0 + i0][d0] = make_float2(r0a, r0b);
    *(float2*)&Rpart[sp][ib0 + i1][d0] = make_float2(r1a, r1b);
    *(float2*)&Vpart[sp][ib0 + i0][d0] = make_float2(v0a, v0b);
    *(float2*)&Vpart[sp][ib0 + i1][d0] = make_float2(v1a, v1b);
}

// ---------------------------------------------------------------------------
// Kernel 3: combine splits + epilogue out = aV + R @ W_Ev + b_Ev
// thread = 1 row x 4 cols.
// ---------------------------------------------------------------------------
__global__ __launch_bounds__(256) void combine_kernel(
    const float* __restrict__ WEv,
    const float* __restrict__ bEv,
    float* __restrict__ out)
{
    __shared__ float Rs[BI * DIM];
    const int tid = threadIdx.x;
    const int ib0 = blockIdx.x * BI;
    const int i   = tid >> 5;
    const int c0  = (tid & 31) * 4;
    const int gi  = ib0 + i;

    float m = -1e30f;
#pragma unroll
    for (int p = 0; p < NSPLIT; p++) m = fmaxf(m, Mpart[p][gi]);
    float s = 0.f;
    float4 r = make_float4(0.f, 0.f, 0.f, 0.f);
    float4 v = make_float4(0.f, 0.f, 0.f, 0.f);
#pragma unroll
    for (int p = 0; p < NSPLIT; p++) {
        float c = __expf(Mpart[p][gi] - m);
        s += Spart[p][gi] * c;
        float4 rp = *(const float4*)&Rpart[p][gi][c0];
        float4 vp = *(const float4*)&Vpart[p][gi][c0];
        r.x += c * rp.x;  r.y += c * rp.y;  r.z += c * rp.z;  r.w += c * rp.w;
        v.x += c * vp.x;  v.y += c * vp.y;  v.z += c * vp.z;  v.w += c * vp.w;
    }
    float inv = 1.f / s;
    r.x *= inv;  r.y *= inv;  r.z *= inv;  r.w *= inv;
    v.x *= inv;  v.y *= inv;  v.z *= inv;  v.w *= inv;

    *(float4*)&Rs[i * DIM + c0] = r;
    __syncthreads();

    float4 o = *(const float4*)(bEv + c0);
    o.x += v.x;  o.y += v.y;  o.z += v.z;  o.w += v.w;
    const float* rrow = Rs + i * DIM;
#pragma unroll 8
    for (int dd = 0; dd < DIM; dd++) {
        float4 w = *(const float4*)(WEv + dd * DIM + c0);
        float rv = rrow[dd];                               // broadcast
        o.x += rv * w.x;  o.y += rv * w.y;
        o.z += rv * w.z;  o.w += rv * w.w;
    }
    *(float4*)(out + gi * DIM + c0) = o;
}

// ---------------------------------------------------------------------------
extern "C" void kernel_launch(void* const* d_in, const int* in_sizes, int n_in,
                              void* d_out, int out_size)
{
    const float* x   = (const float*)d_in[0];
    const float* WQ  = (const float*)d_in[1];
    const float* bQ  = (const float*)d_in[2];
    const float* WK  = (const float*)d_in[3];
    const float* bK  = (const float*)d_in[4];
    const float* WV  = (const float*)d_in[5];
    const float* bV  = (const float*)d_in[6];
    const float* WEv = (const float*)d_in[7];
    const float* bEv = (const float*)d_in[8];
    const float* WA  = (const float*)d_in[9];
    // d_in[10] = b_A: cancels in softmax; unused.
    float* out = (float*)d_out;

    qkv_kernel<<<dim3(128, 3), 256>>>(x, WQ, bQ, WK, bK, WV, bV);
    attn_partial<<<dim3(NTOK / BI, NSPLIT), 256>>>(WA);
    combine_kernel<<<NTOK / BI, 256>>>(WEv, bEv, out);
}

// round 5
// speedup vs baseline: 1.9274x; 1.1258x over previous
#include <cuda_runtime.h>

#define NTOK   1024
#define DIM    128
#define BI     8
#define NSPLIT 4
#define JSPAN  (NTOK / NSPLIT)   // 256

typedef unsigned long long ull;

// ---- packed f32x2 helpers (Blackwell) -------------------------------------
__device__ __forceinline__ ull pack2(float x, float y) {
    ull r; asm("mov.b64 %0, {%1, %2};" : "=l"(r) : "f"(x), "f"(y)); return r;
}
__device__ __forceinline__ void unpack2(ull v, float& x, float& y) {
    asm("mov.b64 {%0, %1}, %2;" : "=f"(x), "=f"(y) : "l"(v));
}
__device__ __forceinline__ ull add2(ull a, ull b) {
    ull r; asm("add.rn.f32x2 %0, %1, %2;" : "=l"(r) : "l"(a), "l"(b)); return r;
}
__device__ __forceinline__ ull fma2(ull a, ull b, ull c) {
    ull r; asm("fma.rn.f32x2 %0, %1, %2, %3;" : "=l"(r) : "l"(a), "l"(b), "l"(c)); return r;
}
__device__ __forceinline__ ull relu2(ull a) {
    float x, y; unpack2(a, x, y);
    return pack2(fmaxf(x, 0.f), fmaxf(y, 0.f));
}

// Scratch (__device__ globals: allocation-free rule)
__device__ float Qg[NTOK * DIM];
__device__ float Kg[NTOK * DIM];
__device__ float Vg[NTOK * DIM];
__device__ float Rpart[NSPLIT][NTOK][DIM];
__device__ float Vpart[NSPLIT][NTOK][DIM];
__device__ float Mpart[NSPLIT][NTOK];
__device__ float Spart[NSPLIT][NTOK];

// ---------------------------------------------------------------------------
// Kernel 1: Q/K/V = x @ W + b. grid (64, 3), 256 thr, 16 rows/block.
// thread = 2 rows x 4 cols -> 8 independent FMA chains per W float4.
// ---------------------------------------------------------------------------
__global__ __launch_bounds__(256) void qkv_kernel(
    const float* __restrict__ x,
    const float* __restrict__ Wq, const float* __restrict__ bq,
    const float* __restrict__ Wk, const float* __restrict__ bk,
    const float* __restrict__ Wv, const float* __restrict__ bv)
{
    __shared__ float xs[16 * DIM];
    const int tid = threadIdx.x;
    const int rt = blockIdx.x;
    const int m  = blockIdx.y;
    const float* W = (m == 0) ? Wq : (m == 1) ? Wk : Wv;
    const float* b = (m == 0) ? bq : (m == 1) ? bk : bv;
    float* outp    = (m == 0) ? Qg : (m == 1) ? Kg : Vg;

    ((float4*)xs)[tid]       = ((const float4*)(x + rt * 16 * DIM))[tid];
    ((float4*)xs)[tid + 256] = ((const float4*)(x + rt * 16 * DIM))[tid + 256];
    __syncthreads();

    const int r0 = (tid >> 5) * 2;       // rows r0, r0+1 (warp-uniform)
    const int c0 = (tid & 31) * 4;
    float4 bias = *(const float4*)(b + c0);
    float4 a0 = bias, a1 = bias;
    const float* x0r = xs + r0 * DIM;
    const float* x1r = xs + (r0 + 1) * DIM;

#pragma unroll 8
    for (int d = 0; d < DIM; d++) {
        float4 w = *(const float4*)(W + d * DIM + c0);
        float x0 = x0r[d];               // broadcast
        float x1 = x1r[d];
        a0.x += x0 * w.x;  a0.y += x0 * w.y;  a0.z += x0 * w.z;  a0.w += x0 * w.w;
        a1.x += x1 * w.x;  a1.y += x1 * w.y;  a1.z += x1 * w.z;  a1.w += x1 * w.w;
    }
    *(float4*)(outp + (rt * 16 + r0) * DIM + c0)     = a0;
    *(float4*)(outp + (rt * 16 + r0 + 1) * DIM + c0) = a1;
}

// ---------------------------------------------------------------------------
// Kernel 2: per-(i-tile, j-split) partial attention, packed f32x2.
// ---------------------------------------------------------------------------
__global__ __launch_bounds__(256) void attn_partial(const float* __restrict__ WA)
{
    __shared__ float es[BI * JSPAN];     // 8 KB
    __shared__ float Qs[BI * DIM];       // 4 KB  (row-major, for phase B)
    __shared__ float QsT[DIM * BI];      // 4 KB  (transposed, for phase A)
    __shared__ ull   WAs2[DIM];          // 1 KB  ((wa,wa) duplicated)

    const int tid = threadIdx.x;
    const int ib0 = blockIdx.x * BI;
    const int sp  = blockIdx.y;
    const int js0 = sp * JSPAN;

    ((float4*)Qs)[tid] = ((const float4*)(Qg + ib0 * DIM))[tid];   // 1024 floats
    for (int k = tid; k < BI * DIM; k += 256)
        QsT[(k & 127) * BI + (k >> 7)] = Qg[ib0 * DIM + k];        // coalesced LDG
    if (tid < DIM) { float w = WA[tid]; WAs2[tid] = pack2(w, w); }
    __syncthreads();

    // ---------------- Phase A: thread owns one j; packed over i-pairs ------
    {
        ull e2[4] = {0ull, 0ull, 0ull, 0ull};   // (e_{2p}, e_{2p+1})
        const float* krow = Kg + (js0 + tid) * DIM;

        for (int db = 0; db < DIM; db += 16) {
            float4 k0 = *(const float4*)(krow + db);
            float4 k1 = *(const float4*)(krow + db + 4);
            float4 k2 = *(const float4*)(krow + db + 8);
            float4 k3 = *(const float4*)(krow + db + 12);
            float kv[16];
            kv[0]=k0.x; kv[1]=k0.y; kv[2]=k0.z; kv[3]=k0.w;
            kv[4]=k1.x; kv[5]=k1.y; kv[6]=k1.z; kv[7]=k1.w;
            kv[8]=k2.x; kv[9]=k2.y; kv[10]=k2.z; kv[11]=k2.w;
            kv[12]=k3.x; kv[13]=k3.y; kv[14]=k3.z; kv[15]=k3.w;
#pragma unroll
            for (int t = 0; t < 16; t++) {
                ull kk2 = pack2(kv[t], kv[t]);           // 1x per d, 4x reuse
                ull wa2 = WAs2[db + t];                  // LDS.64 broadcast
#pragma unroll
                for (int p = 0; p < 4; p++) {
                    ull q2 = *(const ull*)&QsT[(db + t) * BI + 2 * p];  // LDS.64 bcast
                    e2[p] = fma2(relu2(add2(q2, kk2)), wa2, e2[p]);
                }
            }
        }
#pragma unroll
        for (int p = 0; p < 4; p++) {
            float ex, ey; unpack2(e2[p], ex, ey);
            es[(2 * p) * JSPAN + tid]     = ex;
            es[(2 * p + 1) * JSPAN + tid] = ey;
        }
    }
    __syncthreads();

    // ---------------- split-local softmax: warp w -> row w ----------------
    {
        const int w = tid >> 5, lane = tid & 31;
        float* row = es + w * JSPAN;
        float mx = -1e30f;
#pragma unroll
        for (int j = lane; j < JSPAN; j += 32) mx = fmaxf(mx, row[j]);
#pragma unroll
        for (int o = 16; o > 0; o >>= 1) mx = fmaxf(mx, __shfl_xor_sync(0xffffffffu, mx, o));
        float s = 0.f;
#pragma unroll
        for (int j = lane; j < JSPAN; j += 32) {
            float v = __expf(row[j] - mx);
            row[j] = v;                                  // unnormalized p
            s += v;
        }
#pragma unroll
        for (int o = 16; o > 0; o >>= 1) s += __shfl_xor_sync(0xffffffffu, s, o);
        if (lane == 0) {
            Mpart[sp][ib0 + w] = mx;
            Spart[sp][ib0 + w] = s;
        }
    }
    __syncthreads();

    // ---------------- Phase B: packed over d-pairs ------------------------
    const int d0 = (tid & 63) * 2;
    const int ig = tid >> 6;             // warp-uniform
    const int i0 = ig, i1 = ig + 4;
    const ull q02 = *(const ull*)(Qs + i0 * DIM + d0);
    const ull q12 = *(const ull*)(Qs + i1 * DIM + d0);
    ull r0 = 0ull, r1 = 0ull, v0 = 0ull, v1 = 0ull;

    const float* kr  = Kg + js0 * DIM + d0;
    const float* vr  = Vg + js0 * DIM + d0;
    const float* ea0 = es + i0 * JSPAN;
    const float* ea1 = es + i1 * JSPAN;

#pragma unroll 4
    for (int j = 0; j < JSPAN; j++) {
        float a0s = ea0[j];                              // smem broadcast
        float a1s = ea1[j];
        ull a02 = pack2(a0s, a0s);
        ull a12 = pack2(a1s, a1s);
        ull kk  = *(const ull*)(kr + j * DIM);           // LDG.64, L1/L2 hit
        ull vv  = *(const ull*)(vr + j * DIM);
        r0 = fma2(relu2(add2(q02, kk)), a02, r0);
        r1 = fma2(relu2(add2(q12, kk)), a12, r1);
        v0 = fma2(vv, a02, v0);
        v1 = fma2(vv, a12, v1);
    }

    float x, y;
    unpack2(r0, x, y); *(float2*)&Rpart[sp][ib0 + i0][d0] = make_float2(x, y);
    unpack2(r1, x, y); *(float2*)&Rpart[sp][ib0 + i1][d0] = make_float2(x, y);
    unpack2(v0, x, y); *(float2*)&Vpart[sp][ib0 + i0][d0] = make_float2(x, y);
    unpack2(v1, x, y); *(float2*)&Vpart[sp][ib0 + i1][d0] = make_float2(x, y);
}

// ---------------------------------------------------------------------------
// Kernel 3: combine splits + epilogue out = aV + R @ W_Ev + b_Ev
// ---------------------------------------------------------------------------
__global__ __launch_bounds__(256) void combine_kernel(
    const float* __restrict__ WEv,
    const float* __restrict__ bEv,
    float* __restrict__ out)
{
    __shared__ float Rs[BI * DIM];
    const int tid = threadIdx.x;
    const int ib0 = blockIdx.x * BI;
    const int i   = tid >> 5;
    const int c0  = (tid & 31) * 4;
    const int gi  = ib0 + i;

    float m = -1e30f;
#pragma unroll
    for (int p = 0; p < NSPLIT; p++) m = fmaxf(m, Mpart[p][gi]);
    float s = 0.f;
    float4 r = make_float4(0.f, 0.f, 0.f, 0.f);
    float4 v = make_float4(0.f, 0.f, 0.f, 0.f);
#pragma unroll
    for (int p = 0; p < NSPLIT; p++) {
        float c = __expf(Mpart[p][gi] - m);
        s += Spart[p][gi] * c;
        float4 rp = *(const float4*)&Rpart[p][gi][c0];
        float4 vp = *(const float4*)&Vpart[p][gi][c0];
        r.x += c * rp.x;  r.y += c * rp.y;  r.z += c * rp.z;  r.w += c * rp.w;
        v.x += c * vp.x;  v.y += c * vp.y;  v.z += c * vp.z;  v.w += c * vp.w;
    }
    float inv = 1.f / s;
    r.x *= inv;  r.y *= inv;  r.z *= inv;  r.w *= inv;
    v.x *= inv;  v.y *= inv;  v.z *= inv;  v.w *= inv;

    *(float4*)&Rs[i * DIM + c0] = r;
    __syncthreads();

    float4 o = *(const float4*)(bEv + c0);
    o.x += v.x;  o.y += v.y;  o.z += v.z;  o.w += v.w;
    const float* rrow = Rs + i * DIM;
#pragma unroll 8
    for (int dd = 0; dd < DIM; dd++) {
        float4 w = *(const float4*)(WEv + dd * DIM + c0);
        float rv = rrow[dd];                             // broadcast
        o.x += rv * w.x;  o.y += rv * w.y;
        o.z += rv * w.z;  o.w += rv * w.w;
    }
    *(float4*)(out + gi * DIM + c0) = o;
}

// ---------------------------------------------------------------------------
extern "C" void kernel_launch(void* const* d_in, const int* in_sizes, int n_in,
                              void* d_out, int out_size)
{
    const float* x   = (const float*)d_in[0];
    const float* WQ  = (const float*)d_in[1];
    const float* bQ  = (const float*)d_in[2];
    const float* WK  = (const float*)d_in[3];
    const float* bK  = (const float*)d_in[4];
    const float* WV  = (const float*)d_in[5];
    const float* bV  = (const float*)d_in[6];
    const float* WEv = (const float*)d_in[7];
    const float* bEv = (const float*)d_in[8];
    const float* WA  = (const float*)d_in[9];
    // d_in[10] = b_A: cancels in softmax; unused.
    float* out = (float*)d_out;

    qkv_kernel<<<dim3(64, 3), 256>>>(x, WQ, bQ, WK, bK, WV, bV);
    attn_partial<<<dim3(NTOK / BI, NSPLIT), 256>>>(WA);
    combine_kernel<<<NTOK / BI, 256>>>(WEv, bEv, out);
}